// round 1
// baseline (speedup 1.0000x reference)
#include <cuda_runtime.h>
#include <cuda_bf16.h>
#include <mma.h>

using namespace nvcuda;

// Problem dims
#define NTOK 65536
#define DIM  1024
#define HID  512
#define HHALF 256
#define NREG 16
#define MPER 4096   // tokens per region

// ---------------- scratch (device globals; no runtime alloc allowed) ----------
__device__ __nv_bfloat16 g_H[(long)NTOK * HID];     // region_emb (post-GELU), bf16, 67MB
__device__ __nv_bfloat16 g_T[(long)NTOK * HHALF];   // tanh(h@Wa1+ba1), bf16, 33MB
__device__ float g_scores[NTOK];
__device__ float g_stats[32];                        // [0:16) max, [16:32) sumexp
__device__ float g_rf[NREG * HID];                   // region_features fp32

__device__ __forceinline__ float gelu_exact(float v) {
    return 0.5f * v * (1.0f + erff(v * 0.7071067811865475f));
}

// ---------------- tiled wmma GEMM: C = act(A @ B + bias) ----------------------
// MODE 0: A = embeddings fp32 [NTOK,1024], B = W1 [1024,512], act=GELU, C=g_H
// MODE 1: A = g_H bf16 [NTOK,512],        B = Wa1 [512,256], act=tanh, C=g_T
// CTA tile 128x64, BK=32, 8 warps (4x2) each 32x32, double-buffered smem.
#define BM 128
#define BN 64
#define BK 32
#define SA 48   // padded stride (elements) for A smem tile
#define SB 80   // padded stride for B smem tile

template<int MODE>
__global__ __launch_bounds__(256)
void gemm_bias_act(const float* __restrict__ Af,
                   const float* __restrict__ B,
                   const float* __restrict__ bias)
{
    constexpr int K  = (MODE == 0) ? DIM : HID;
    constexpr int Nn = (MODE == 0) ? HID : HHALF;
    __nv_bfloat16* Cp = (MODE == 0) ? g_H : g_T;

    // stage buffers: As 2*128*48*2B = 24576, Bs 2*32*80*2B = 10240 -> 34816
    // epilogue reuses same storage as 8*1024 floats = 32768
    __shared__ __align__(16) unsigned char smem_raw[34816];
    __nv_bfloat16* As0 = (__nv_bfloat16*)(smem_raw);
    __nv_bfloat16* As1 = (__nv_bfloat16*)(smem_raw + 12288);
    __nv_bfloat16* Bs0 = (__nv_bfloat16*)(smem_raw + 24576);
    __nv_bfloat16* Bs1 = (__nv_bfloat16*)(smem_raw + 29696);

    const int tid  = threadIdx.x;
    const int warp = tid >> 5;
    const int lane = tid & 31;
    const int wm   = warp >> 1;  // 0..3
    const int wn   = warp & 1;   // 0..1
    const long row0 = (long)blockIdx.y * BM;
    const int  col0 = blockIdx.x * BN;

    wmma::fragment<wmma::accumulator, 16, 16, 16, float> acc[2][2];
    #pragma unroll
    for (int i = 0; i < 2; i++)
        #pragma unroll
        for (int j = 0; j < 2; j++)
            wmma::fill_fragment(acc[i][j], 0.0f);

    auto loadTiles = [&](__nv_bfloat16* As, __nv_bfloat16* Bs, int k0) {
        if (MODE == 0) {
            // A fp32 -> bf16
            #pragma unroll
            for (int i = tid; i < BM * BK / 4; i += 256) {
                int r = i >> 3, c = (i & 7) * 4;
                float4 v = *(const float4*)&Af[(row0 + r) * (long)K + k0 + c];
                __nv_bfloat16* p = &As[r * SA + c];
                p[0] = __float2bfloat16(v.x); p[1] = __float2bfloat16(v.y);
                p[2] = __float2bfloat16(v.z); p[3] = __float2bfloat16(v.w);
            }
        } else {
            const __nv_bfloat16* Ab = g_H;
            #pragma unroll
            for (int i = tid; i < BM * BK / 8; i += 256) {
                int r = i >> 2, c = (i & 3) * 8;
                uint4 v = *(const uint4*)&Ab[(row0 + r) * (long)K + k0 + c];
                *(uint4*)&As[r * SA + c] = v;
            }
        }
        // B fp32 [K][Nn] -> bf16 tile [BK][BN]
        #pragma unroll
        for (int i = tid; i < BK * BN / 4; i += 256) {
            int r = i >> 4, c = (i & 15) * 4;
            float4 v = *(const float4*)&B[(long)(k0 + r) * Nn + col0 + c];
            __nv_bfloat16* p = &Bs[r * SB + c];
            p[0] = __float2bfloat16(v.x); p[1] = __float2bfloat16(v.y);
            p[2] = __float2bfloat16(v.z); p[3] = __float2bfloat16(v.w);
        }
    };

    constexpr int NK = K / BK;
    loadTiles(As0, Bs0, 0);
    __syncthreads();

    #pragma unroll 1
    for (int ks = 0; ks < NK; ks++) {
        __nv_bfloat16* Asb = (ks & 1) ? As1 : As0;
        __nv_bfloat16* Bsb = (ks & 1) ? Bs1 : Bs0;
        if (ks + 1 < NK) {
            __nv_bfloat16* Asn = (ks & 1) ? As0 : As1;
            __nv_bfloat16* Bsn = (ks & 1) ? Bs0 : Bs1;
            loadTiles(Asn, Bsn, (ks + 1) * BK);
        }
        #pragma unroll
        for (int kk = 0; kk < 2; kk++) {
            wmma::fragment<wmma::matrix_a, 16, 16, 16, __nv_bfloat16, wmma::row_major> af[2];
            wmma::fragment<wmma::matrix_b, 16, 16, 16, __nv_bfloat16, wmma::row_major> bf[2];
            #pragma unroll
            for (int i = 0; i < 2; i++)
                wmma::load_matrix_sync(af[i], &Asb[(wm * 32 + i * 16) * SA + kk * 16], SA);
            #pragma unroll
            for (int j = 0; j < 2; j++)
                wmma::load_matrix_sync(bf[j], &Bsb[(kk * 16) * SB + wn * 32 + j * 16], SB);
            #pragma unroll
            for (int i = 0; i < 2; i++)
                #pragma unroll
                for (int j = 0; j < 2; j++)
                    wmma::mma_sync(acc[i][j], af[i], bf[j], acc[i][j]);
        }
        __syncthreads();
    }

    // epilogue: bias + activation + bf16 store
    float* Cs = (float*)smem_raw;
    float* cw = Cs + warp * 1024;
    #pragma unroll
    for (int i = 0; i < 2; i++)
        #pragma unroll
        for (int j = 0; j < 2; j++)
            wmma::store_matrix_sync(&cw[i * 16 * 32 + j * 16], acc[i][j], 32, wmma::mem_row_major);
    __syncwarp();
    #pragma unroll
    for (int e = lane; e < 1024; e += 32) {
        int r = e >> 5, c = e & 31;
        long gr = row0 + wm * 32 + r;
        int  gc = col0 + wn * 32 + c;
        float v = cw[e] + bias[gc];
        if (MODE == 0) v = gelu_exact(v);
        else           v = tanhf(v);
        Cp[gr * (long)Nn + gc] = __float2bfloat16(v);
    }
}

// ---------------- score reduce: s[i] = T[i,:] . Wa2 + ba2 ---------------------
__global__ __launch_bounds__(256)
void score_reduce(const float* __restrict__ Wa2, const float* __restrict__ ba2)
{
    __shared__ float w2[HHALF];
    for (int i = threadIdx.x; i < HHALF; i += blockDim.x) w2[i] = Wa2[i];
    __syncthreads();
    int warp = threadIdx.x >> 5, lane = threadIdx.x & 31;
    long tok = (long)blockIdx.x * 8 + warp;
    const __nv_bfloat16* row = g_T + tok * HHALF;
    uint4 v = *(const uint4*)&row[lane * 8];
    const __nv_bfloat16* p = (const __nv_bfloat16*)&v;
    float acc = 0.f;
    #pragma unroll
    for (int j = 0; j < 8; j++) acc += __bfloat162float(p[j]) * w2[lane * 8 + j];
    #pragma unroll
    for (int o = 16; o; o >>= 1) acc += __shfl_xor_sync(0xffffffffu, acc, o);
    if (lane == 0) g_scores[tok] = acc + ba2[0];
}

// ---------------- per-region softmax stats ------------------------------------
__global__ __launch_bounds__(256)
void region_softmax_stats()
{
    int r = blockIdx.x, tid = threadIdx.x;
    __shared__ float red[256];
    float mx = -1e30f;
    for (int m = tid; m < MPER; m += 256) mx = fmaxf(mx, g_scores[m * NREG + r]);
    red[tid] = mx; __syncthreads();
    for (int s = 128; s; s >>= 1) { if (tid < s) red[tid] = fmaxf(red[tid], red[tid + s]); __syncthreads(); }
    mx = red[0]; __syncthreads();
    float se = 0.f;
    for (int m = tid; m < MPER; m += 256) se += expf(g_scores[m * NREG + r] - mx);
    red[tid] = se; __syncthreads();
    for (int s = 128; s; s >>= 1) { if (tid < s) red[tid] += red[tid + s]; __syncthreads(); }
    if (tid == 0) { g_stats[r] = mx; g_stats[16 + r] = red[0]; }
}

// ---------------- weighted pooling: region_features ---------------------------
__global__ __launch_bounds__(256)
void region_pool()
{
    int r = blockIdx.x, chunk = blockIdx.y, tid = threadIdx.x;
    __shared__ float w[MPER];
    __shared__ float part[256];
    float mx = g_stats[r], inv = 1.0f / g_stats[16 + r];
    for (int m = tid; m < MPER; m += 256) w[m] = expf(g_scores[m * NREG + r] - mx);
    __syncthreads();
    int h = chunk * 128 + (tid & 127);
    int half = tid >> 7;
    float acc = 0.f;
    for (int m = half; m < MPER; m += 2)
        acc += w[m] * __bfloat162float(g_H[((long)(m * NREG + r)) * HID + h]);
    part[tid] = acc; __syncthreads();
    if (half == 0) g_rf[r * HID + h] = (part[tid] + part[tid + 128]) * inv;
}

// ---------------- tail: slide encoder + attention + classifier (fp32) ---------
__global__ __launch_bounds__(512)
void tail_kernel(const float* __restrict__ Ws,  const float* __restrict__ bs,
                 const float* __restrict__ Wsa1,const float* __restrict__ bsa1,
                 const float* __restrict__ Wsa2,const float* __restrict__ bsa2,
                 const float* __restrict__ Wc1, const float* __restrict__ bc1,
                 const float* __restrict__ Wc2, const float* __restrict__ bc2,
                 float* __restrict__ out)
{
    __shared__ float se[NREG * HID];   // 32KB
    __shared__ float sattn[NREG];
    __shared__ float srep[HID];
    __shared__ float c1[HHALF];
    __shared__ float red[64];
    int tid = threadIdx.x;

    // slide_emb = gelu(rf @ Ws + bs)
    {
        int j = tid;  // 0..511
        float acc[NREG];
        #pragma unroll
        for (int r = 0; r < NREG; r++) acc[r] = 0.f;
        for (int k = 0; k < HID; k++) {
            float wv = Ws[k * HID + j];
            #pragma unroll
            for (int r = 0; r < NREG; r++) acc[r] += g_rf[r * HID + k] * wv;
        }
        #pragma unroll
        for (int r = 0; r < NREG; r++)
            se[r * HID + j] = gelu_exact(acc[r] + bs[j]);
    }
    if (tid < NREG) sattn[tid] = 0.f;
    __syncthreads();

    // slide attention scores
    {
        int j = tid & 255;
        int g = tid >> 8;  // 0..1 -> regions [g*8, g*8+8)
        for (int r = g * 8; r < g * 8 + 8; r++) {
            float acc = 0.f;
            for (int k = 0; k < HID; k++) acc += se[r * HID + k] * Wsa1[k * HHALF + j];
            float u = tanhf(acc + bsa1[j]);
            atomicAdd(&sattn[r], u * Wsa2[j]);
        }
    }
    __syncthreads();

    if (tid == 0) {
        float mx = -1e30f;
        for (int r = 0; r < NREG; r++) { sattn[r] += bsa2[0]; mx = fmaxf(mx, sattn[r]); }
        float s = 0.f;
        for (int r = 0; r < NREG; r++) { sattn[r] = expf(sattn[r] - mx); s += sattn[r]; }
        for (int r = 0; r < NREG; r++) sattn[r] /= s;
    }
    __syncthreads();

    // slide_rep
    {
        float acc = 0.f;
        #pragma unroll
        for (int r = 0; r < NREG; r++) acc += sattn[r] * se[r * HID + tid];
        srep[tid] = acc;
    }
    __syncthreads();

    // classifier L1
    if (tid < HHALF) {
        float acc = 0.f;
        for (int k = 0; k < HID; k++) acc += srep[k] * Wc1[k * HHALF + tid];
        c1[tid] = gelu_exact(acc + bc1[tid]);
    }
    __syncthreads();

    // logits
    if (tid < 64) {
        int o = tid & 1, p = tid >> 1;
        float acc = 0.f;
        for (int k = p; k < HHALF; k += 32) acc += c1[k] * Wc2[k * 2 + o];
        red[tid] = acc;
    }
    __syncthreads();
    if (tid < 2) {
        float acc = bc2[tid];
        #pragma unroll
        for (int p = 0; p < 32; p++) acc += red[p * 2 + tid];
        out[tid] = acc;
    }
}

// ---------------- launch --------------------------------------------------------
extern "C" void kernel_launch(void* const* d_in, const int* in_sizes, int n_in,
                              void* d_out, int out_size)
{
    const float* emb  = (const float*)d_in[0];
    const float* W1   = (const float*)d_in[1];
    const float* b1   = (const float*)d_in[2];
    const float* Wa1  = (const float*)d_in[3];
    const float* ba1  = (const float*)d_in[4];
    const float* Wa2  = (const float*)d_in[5];
    const float* ba2  = (const float*)d_in[6];
    const float* Ws   = (const float*)d_in[7];
    const float* bs   = (const float*)d_in[8];
    const float* Wsa1 = (const float*)d_in[9];
    const float* bsa1 = (const float*)d_in[10];
    const float* Wsa2 = (const float*)d_in[11];
    const float* bsa2 = (const float*)d_in[12];
    const float* Wc1  = (const float*)d_in[13];
    const float* bc1  = (const float*)d_in[14];
    const float* Wc2  = (const float*)d_in[15];
    const float* bc2  = (const float*)d_in[16];
    float* out = (float*)d_out;

    // K1: region encoder GEMM + GELU  (65536x1024 @ 1024x512)
    gemm_bias_act<0><<<dim3(HID / BN, NTOK / BM), 256>>>(emb, W1, b1);
    // K2: attention hidden GEMM + tanh (65536x512 @ 512x256)
    gemm_bias_act<1><<<dim3(HHALF / BN, NTOK / BM), 256>>>(nullptr, Wa1, ba1);
    // K2b: scores
    score_reduce<<<NTOK / 8, 256>>>(Wa2, ba2);
    // K3a: per-region softmax stats
    region_softmax_stats<<<NREG, 256>>>();
    // K3b: weighted pooling -> region_features
    region_pool<<<dim3(NREG, HID / 128), 256>>>();
    // K4: tail (slide encoder + attention + classifier)
    tail_kernel<<<1, 512>>>(Ws, bs, Wsa1, bsa1, Wsa2, bsa2, Wc1, bc1, Wc2, bc2, out);
}

// round 4
// speedup vs baseline: 1.5062x; 1.5062x over previous
#include <cuda_runtime.h>
#include <cuda_bf16.h>
#include <cstdint>

// Problem dims
#define NTOK 65536
#define DIM  1024
#define HID  512
#define HHALF 256
#define NREG 16
#define MPER 4096

// ---------------- device scratch ----------------
__device__ __nv_bfloat16 g_H[(long)NTOK * HID];       // region_emb post-GELU (bf16)
__device__ __nv_bfloat16 g_Wt1[HID * DIM];            // W1^T  [N=512,K=1024] bf16
__device__ __nv_bfloat16 g_Wt2[HHALF * HID];          // Wa1^T [N=256,K=512] bf16
__device__ float g_scores_t[NTOK];                    // region-transposed: [r][m]
__device__ float g_stats[32];                         // [0:16) max, [16:32) sumexp
__device__ float g_rf[NREG * HID];

__device__ __forceinline__ float gelu_exact(float v) {
    return 0.5f * v * (1.0f + erff(v * 0.7071067811865475f));
}

// ---------------- helpers ----------------
__device__ __forceinline__ uint32_t smem_u32(const void* p) {
    uint32_t a;
    asm("{ .reg .u64 t; cvta.to.shared.u64 t, %1; cvt.u32.u64 %0, t; }" : "=r"(a) : "l"(p));
    return a;
}
__device__ __forceinline__ uint32_t bf2u(__nv_bfloat162 v) { return *reinterpret_cast<uint32_t*>(&v); }

// SW128-style swizzle on byte offsets within a tile of 128B rows
#define SWZ(o) ((o) ^ (((o) >> 3) & 0x70))

#define CP16(d, s) asm volatile("cp.async.cg.shared.global [%0],[%1],16;" :: "r"(d), "l"(s))
#define CP_COMMIT  asm volatile("cp.async.commit_group;" ::: "memory")
#define CP_WAIT0   asm volatile("cp.async.wait_group 0;" ::: "memory")

// ---------------- weight transpose+convert: fp32 [K,N] -> bf16 [N,K] ---------
__global__ __launch_bounds__(256)
void transpose_conv(const float* __restrict__ src, __nv_bfloat16* __restrict__ dst,
                    int K, int N)
{
    __shared__ float t[32][33];
    int nb = blockIdx.x * 32, kb = blockIdx.y * 32;
    int x = threadIdx.x & 31, y = threadIdx.x >> 5;
    #pragma unroll
    for (int i = 0; i < 32; i += 8) t[y + i][x] = src[(long)(kb + y + i) * N + nb + x];
    __syncthreads();
    #pragma unroll
    for (int i = 0; i < 32; i += 8)
        dst[(long)(nb + y + i) * K + kb + x] = __float2bfloat16(t[x][y + i]);
}

__global__ __launch_bounds__(256)
void scores_init(const float* __restrict__ ba2)
{
    g_scores_t[blockIdx.x * 256 + threadIdx.x] = ba2[0];
}

// ---------------- mma.sync GEMM (HMMA path; no 'a' features) ------------------
// CTA tile 128x128, BK=64, 8 warps (2 m x 4 n), warp tile 64x32.
// MODE 0: A = emb fp32 [NTOK,1024] (LDG+cvt staged), B = g_Wt1; epilogue GELU -> g_H
// MODE 1: A = g_H bf16 (cp.async),  B = g_Wt2;       epilogue tanh-dot -> atomic scores
#define STAGE 32768            // A 128x64 bf16 (16KB) + B 128x64 bf16 (16KB)
#define SMEM_REQ (2 * STAGE + 1024)

template<int KDIM, int MODE>
__global__ __launch_bounds__(256)
void mma_gemm(const float* __restrict__ Af, const float* __restrict__ biasp,
              const float* __restrict__ Wa2p, const float* __restrict__ ba2p)
{
    extern __shared__ unsigned char smem[];
    constexpr int NCH = KDIM / 64;
    const int tid = threadIdx.x, warp = tid >> 5, lane = tid & 31;
    const int wm = warp >> 2, wn = warp & 3;
    const long row0 = (long)blockIdx.y * 128;
    const int col0 = blockIdx.x * 128;

    uint32_t sbb = smem_u32(smem);
    float* bias_s = (float*)(smem + 2 * STAGE);
    float* w2_s = bias_s + 128;
    if (tid < 128) {
        bias_s[tid] = biasp[col0 + tid];
        if (MODE == 1) w2_s[tid] = Wa2p[col0 + tid];
    }

    const __nv_bfloat16* Bt = (MODE == 0) ? g_Wt1 : g_Wt2;

    float4 ar[8];
    auto ldgA = [&](int kc) {
        #pragma unroll
        for (int i = 0; i < 4; i++) {
            int u = tid + 256 * i, row = u >> 3, cu = u & 7;
            const float4* s = (const float4*)(Af + (row0 + row) * (long)KDIM + kc * 64 + cu * 8);
            ar[2 * i] = s[0]; ar[2 * i + 1] = s[1];
        }
    };
    auto stsA = [&](int sbuf) {
        #pragma unroll
        for (int i = 0; i < 4; i++) {
            int u = tid + 256 * i, row = u >> 3, cu = u & 7;
            uint4 p;
            p.x = bf2u(__floats2bfloat162_rn(ar[2*i].x,   ar[2*i].y));
            p.y = bf2u(__floats2bfloat162_rn(ar[2*i].z,   ar[2*i].w));
            p.z = bf2u(__floats2bfloat162_rn(ar[2*i+1].x, ar[2*i+1].y));
            p.w = bf2u(__floats2bfloat162_rn(ar[2*i+1].z, ar[2*i+1].w));
            *(uint4*)(smem + sbuf * STAGE + SWZ((uint32_t)(row * 128 + cu * 16))) = p;
        }
    };
    auto cpA = [&](int sbuf, int kc) {
        #pragma unroll
        for (int i = 0; i < 4; i++) {
            int u = tid + 256 * i, row = u >> 3, cu = u & 7;
            CP16(sbb + sbuf * STAGE + SWZ((uint32_t)(row * 128 + cu * 16)),
                 (const void*)(g_H + (row0 + row) * (long)KDIM + kc * 64 + cu * 8));
        }
    };
    auto cpB = [&](int sbuf, int kc) {
        #pragma unroll
        for (int i = 0; i < 4; i++) {
            int u = tid + 256 * i, row = u >> 3, cu = u & 7;
            CP16(sbb + sbuf * STAGE + 16384 + SWZ((uint32_t)(row * 128 + cu * 16)),
                 (const void*)(Bt + (col0 + row) * (long)KDIM + kc * 64 + cu * 8));
        }
    };

    float acc[4][4][4];
    #pragma unroll
    for (int mi = 0; mi < 4; mi++)
        #pragma unroll
        for (int ni = 0; ni < 4; ni++)
            #pragma unroll
            for (int q = 0; q < 4; q++) acc[mi][ni][q] = 0.0f;

    // prologue: chunk 0 into buf 0
    if (MODE == 0) ldgA(0); else cpA(0, 0);
    cpB(0, 0);
    CP_COMMIT;
    if (MODE == 0) stsA(0);
    CP_WAIT0;
    __syncthreads();

    #pragma unroll 1
    for (int kc = 0; kc < NCH; kc++) {
        const int s = kc & 1;
        if (kc + 1 < NCH) {
            if (MODE == 0) ldgA(kc + 1); else cpA(s ^ 1, kc + 1);
            cpB(s ^ 1, kc + 1);
            CP_COMMIT;
        }
        uint32_t Ab = sbb + s * STAGE, Bb = Ab + 16384;
        #pragma unroll
        for (int kk = 0; kk < 4; kk++) {
            uint32_t af[4][4], bfr[4][2];
            #pragma unroll
            for (int mi = 0; mi < 4; mi++) {
                int row = wm * 64 + mi * 16 + (lane & 15);
                uint32_t ad = Ab + SWZ((uint32_t)(row * 128 + kk * 32 + ((lane >> 4) << 4)));
                asm volatile("ldmatrix.sync.aligned.m8n8.x4.shared.b16 {%0,%1,%2,%3},[%4];"
                    : "=r"(af[mi][0]), "=r"(af[mi][1]), "=r"(af[mi][2]), "=r"(af[mi][3])
                    : "r"(ad));
            }
            #pragma unroll
            for (int ni = 0; ni < 4; ni++) {
                int row = wn * 32 + ni * 8 + (lane & 7);
                uint32_t bd = Bb + SWZ((uint32_t)(row * 128 + kk * 32 + (((lane >> 3) & 1) << 4)));
                asm volatile("ldmatrix.sync.aligned.m8n8.x2.shared.b16 {%0,%1},[%2];"
                    : "=r"(bfr[ni][0]), "=r"(bfr[ni][1]) : "r"(bd));
            }
            #pragma unroll
            for (int mi = 0; mi < 4; mi++)
                #pragma unroll
                for (int ni = 0; ni < 4; ni++)
                    asm volatile("mma.sync.aligned.m16n8k16.row.col.f32.bf16.bf16.f32 "
                        "{%0,%1,%2,%3},{%4,%5,%6,%7},{%8,%9},{%0,%1,%2,%3};"
                        : "+f"(acc[mi][ni][0]), "+f"(acc[mi][ni][1]),
                          "+f"(acc[mi][ni][2]), "+f"(acc[mi][ni][3])
                        : "r"(af[mi][0]), "r"(af[mi][1]), "r"(af[mi][2]), "r"(af[mi][3]),
                          "r"(bfr[ni][0]), "r"(bfr[ni][1]));
        }
        if (kc + 1 < NCH && MODE == 0) stsA(s ^ 1);
        CP_WAIT0;
        __syncthreads();
    }

    // ---- epilogue ----
    if (MODE == 0) {
        #pragma unroll
        for (int mi = 0; mi < 4; mi++) {
            long r0 = row0 + wm * 64 + mi * 16 + (lane >> 2);
            #pragma unroll
            for (int ni = 0; ni < 4; ni++) {
                int col = wn * 32 + ni * 8 + ((lane & 3) << 1);
                float b0 = bias_s[col], b1 = bias_s[col + 1];
                float* c = acc[mi][ni];
                uint32_t p0 = bf2u(__floats2bfloat162_rn(gelu_exact(c[0] + b0), gelu_exact(c[1] + b1)));
                uint32_t p1 = bf2u(__floats2bfloat162_rn(gelu_exact(c[2] + b0), gelu_exact(c[3] + b1)));
                *(uint32_t*)(g_H + r0 * HID + col0 + col) = p0;
                *(uint32_t*)(g_H + (r0 + 8) * HID + col0 + col) = p1;
            }
        }
    } else {
        #pragma unroll
        for (int mi = 0; mi < 4; mi++) {
            float s0 = 0.f, s1 = 0.f;
            #pragma unroll
            for (int ni = 0; ni < 4; ni++) {
                int col = wn * 32 + ni * 8 + ((lane & 3) << 1);
                float b0 = bias_s[col], b1 = bias_s[col + 1];
                float w0 = w2_s[col], w1 = w2_s[col + 1];
                float* c = acc[mi][ni];
                s0 += tanhf(c[0] + b0) * w0 + tanhf(c[1] + b1) * w1;
                s1 += tanhf(c[2] + b0) * w0 + tanhf(c[3] + b1) * w1;
            }
            s0 += __shfl_xor_sync(0xffffffffu, s0, 1);
            s0 += __shfl_xor_sync(0xffffffffu, s0, 2);
            s1 += __shfl_xor_sync(0xffffffffu, s1, 1);
            s1 += __shfl_xor_sync(0xffffffffu, s1, 2);
            if ((lane & 3) == 0) {
                long r0 = row0 + wm * 64 + mi * 16 + (lane >> 2);
                long r1 = r0 + 8;
                atomicAdd(&g_scores_t[(r0 & 15) * MPER + (r0 >> 4)], s0);
                atomicAdd(&g_scores_t[(r1 & 15) * MPER + (r1 >> 4)], s1);
            }
        }
    }
}

// ---------------- per-region softmax stats ------------------------------------
__global__ __launch_bounds__(256)
void region_softmax_stats()
{
    int r = blockIdx.x, tid = threadIdx.x;
    __shared__ float red[256];
    const float* sp = g_scores_t + r * MPER;
    float mx = -1e30f;
    for (int m = tid; m < MPER; m += 256) mx = fmaxf(mx, sp[m]);
    red[tid] = mx; __syncthreads();
    for (int s = 128; s; s >>= 1) { if (tid < s) red[tid] = fmaxf(red[tid], red[tid + s]); __syncthreads(); }
    mx = red[0]; __syncthreads();
    float se = 0.f;
    for (int m = tid; m < MPER; m += 256) se += expf(sp[m] - mx);
    red[tid] = se; __syncthreads();
    for (int s = 128; s; s >>= 1) { if (tid < s) red[tid] += red[tid + s]; __syncthreads(); }
    if (tid == 0) { g_stats[r] = mx; g_stats[16 + r] = red[0]; }
}

// ---------------- weighted pooling -------------------------------------------
__global__ __launch_bounds__(256)
void region_pool()
{
    int r = blockIdx.x, chunk = blockIdx.y, tid = threadIdx.x;
    __shared__ float w[MPER];
    __shared__ float part[256];
    float mx = g_stats[r], inv = 1.0f / g_stats[16 + r];
    const float* sp = g_scores_t + r * MPER;
    for (int m = tid; m < MPER; m += 256) w[m] = expf(sp[m] - mx);
    __syncthreads();
    int h = chunk * 128 + (tid & 127);
    int half = tid >> 7;
    float acc = 0.f;
    for (int m = half; m < MPER; m += 2)
        acc += w[m] * __bfloat162float(g_H[((long)(m * NREG + r)) * HID + h]);
    part[tid] = acc; __syncthreads();
    if (half == 0) g_rf[r * HID + h] = (part[tid] + part[tid + 128]) * inv;
}

// ---------------- tail ---------------------------------------------------------
__global__ __launch_bounds__(512)
void tail_kernel(const float* __restrict__ Ws,  const float* __restrict__ bs,
                 const float* __restrict__ Wsa1,const float* __restrict__ bsa1,
                 const float* __restrict__ Wsa2,const float* __restrict__ bsa2,
                 const float* __restrict__ Wc1, const float* __restrict__ bc1,
                 const float* __restrict__ Wc2, const float* __restrict__ bc2,
                 float* __restrict__ out)
{
    __shared__ float se[NREG * HID];
    __shared__ float sattn[NREG];
    __shared__ float srep[HID];
    __shared__ float c1[HHALF];
    __shared__ float red[64];
    int tid = threadIdx.x;

    {
        int j = tid;
        float acc[NREG];
        #pragma unroll
        for (int r = 0; r < NREG; r++) acc[r] = 0.f;
        for (int k = 0; k < HID; k++) {
            float wv = Ws[k * HID + j];
            #pragma unroll
            for (int r = 0; r < NREG; r++) acc[r] += g_rf[r * HID + k] * wv;
        }
        #pragma unroll
        for (int r = 0; r < NREG; r++)
            se[r * HID + j] = gelu_exact(acc[r] + bs[j]);
    }
    if (tid < NREG) sattn[tid] = 0.f;
    __syncthreads();

    {
        int j = tid & 255;
        int g = tid >> 8;
        for (int r = g * 8; r < g * 8 + 8; r++) {
            float acc = 0.f;
            for (int k = 0; k < HID; k++) acc += se[r * HID + k] * Wsa1[k * HHALF + j];
            float u = tanhf(acc + bsa1[j]);
            atomicAdd(&sattn[r], u * Wsa2[j]);
        }
    }
    __syncthreads();

    if (tid == 0) {
        float mx = -1e30f;
        for (int r = 0; r < NREG; r++) { sattn[r] += bsa2[0]; mx = fmaxf(mx, sattn[r]); }
        float s = 0.f;
        for (int r = 0; r < NREG; r++) { sattn[r] = expf(sattn[r] - mx); s += sattn[r]; }
        for (int r = 0; r < NREG; r++) sattn[r] /= s;
    }
    __syncthreads();

    {
        float acc = 0.f;
        #pragma unroll
        for (int r = 0; r < NREG; r++) acc += sattn[r] * se[r * HID + tid];
        srep[tid] = acc;
    }
    __syncthreads();

    if (tid < HHALF) {
        float acc = 0.f;
        for (int k = 0; k < HID; k++) acc += srep[k] * Wc1[k * HHALF + tid];
        c1[tid] = gelu_exact(acc + bc1[tid]);
    }
    __syncthreads();

    if (tid < 64) {
        int o = tid & 1, p = tid >> 1;
        float acc = 0.f;
        for (int k = p; k < HHALF; k += 32) acc += c1[k] * Wc2[k * 2 + o];
        red[tid] = acc;
    }
    __syncthreads();
    if (tid < 2) {
        float acc = bc2[tid];
        #pragma unroll
        for (int p = 0; p < 32; p++) acc += red[p * 2 + tid];
        out[tid] = acc;
    }
}

// ---------------- launch ------------------------------------------------------
extern "C" void kernel_launch(void* const* d_in, const int* in_sizes, int n_in,
                              void* d_out, int out_size)
{
    const float* emb  = (const float*)d_in[0];
    const float* W1   = (const float*)d_in[1];
    const float* b1   = (const float*)d_in[2];
    const float* Wa1  = (const float*)d_in[3];
    const float* ba1  = (const float*)d_in[4];
    const float* Wa2  = (const float*)d_in[5];
    const float* ba2  = (const float*)d_in[6];
    const float* Ws   = (const float*)d_in[7];
    const float* bs   = (const float*)d_in[8];
    const float* Wsa1 = (const float*)d_in[9];
    const float* bsa1 = (const float*)d_in[10];
    const float* Wsa2 = (const float*)d_in[11];
    const float* bsa2 = (const float*)d_in[12];
    const float* Wc1  = (const float*)d_in[13];
    const float* bc1  = (const float*)d_in[14];
    const float* Wc2  = (const float*)d_in[15];
    const float* bc2  = (const float*)d_in[16];
    float* out = (float*)d_out;

    cudaFuncSetAttribute(mma_gemm<DIM, 0>, cudaFuncAttributeMaxDynamicSharedMemorySize, SMEM_REQ);
    cudaFuncSetAttribute(mma_gemm<HID, 1>, cudaFuncAttributeMaxDynamicSharedMemorySize, SMEM_REQ);

    __nv_bfloat16 *wt1, *wt2;
    cudaGetSymbolAddress((void**)&wt1, g_Wt1);
    cudaGetSymbolAddress((void**)&wt2, g_Wt2);
    transpose_conv<<<dim3(HID / 32, DIM / 32), 256>>>(W1, wt1, DIM, HID);
    transpose_conv<<<dim3(HHALF / 32, HID / 32), 256>>>(Wa1, wt2, HID, HHALF);
    scores_init<<<NTOK / 256, 256>>>(ba2);

    // K1: region encoder (65536x1024 @ 1024x512) + GELU -> g_H
    mma_gemm<DIM, 0><<<dim3(HID / 128, NTOK / 128), 256, SMEM_REQ>>>(emb, b1, nullptr, nullptr);
    // K2: attention hidden (65536x512 @ 512x256) + fused tanh-dot -> scores
    mma_gemm<HID, 1><<<dim3(HHALF / 128, NTOK / 128), 256, SMEM_REQ>>>(nullptr, ba1, Wa2, ba2);

    region_softmax_stats<<<NREG, 256>>>();
    region_pool<<<dim3(NREG, HID / 128), 256>>>();
    tail_kernel<<<1, 512>>>(Ws, bs, Wsa1, bsa1, Wsa2, bsa2, Wc1, bc1, Wc2, bc2, out);
}

// round 7
// speedup vs baseline: 1.5418x; 1.0236x over previous
#include <cuda_runtime.h>
#include <cuda_bf16.h>
#include <cstdint>

// Problem dims
#define NTOK 65536
#define DIM  1024
#define HID  512
#define HHALF 256
#define NREG 16
#define MPER 4096

// ---------------- device scratch ----------------
__device__ __nv_bfloat16 g_H[(long)NTOK * HID];       // region_emb post-GELU (bf16)
__device__ __nv_bfloat16 g_Wt1[HID * DIM];            // W1^T  [N=512,K=1024] bf16
__device__ __nv_bfloat16 g_Wt2[HHALF * HID];          // Wa1^T [N=256,K=512] bf16
__device__ float g_scores_t[NTOK];                    // region-transposed: [r][m]
__device__ float g_stats[32];                         // [0:16) max, [16:32) sumexp
__device__ float g_rf[NREG * HID];

__device__ __forceinline__ float gelu_exact(float v) {
    return 0.5f * v * (1.0f + erff(v * 0.7071067811865475f));
}

// ---------------- helpers ----------------
__device__ __forceinline__ uint32_t smem_u32(const void* p) {
    uint32_t a;
    asm("{ .reg .u64 t; cvta.to.shared.u64 t, %1; cvt.u32.u64 %0, t; }" : "=r"(a) : "l"(p));
    return a;
}
__device__ __forceinline__ uint32_t bf2u(__nv_bfloat162 v) { return *reinterpret_cast<uint32_t*>(&v); }

// SW128-style swizzle on byte offsets within a tile of 128B rows
#define SWZ(o) ((o) ^ (((o) >> 3) & 0x70))

#define CP16(d, s) asm volatile("cp.async.cg.shared.global [%0],[%1],16;" :: "r"(d), "l"(s))
#define CP_COMMIT  asm volatile("cp.async.commit_group;" ::: "memory")
#define CP_WAIT0   asm volatile("cp.async.wait_group 0;" ::: "memory")

// ---------------- weight transpose+convert: fp32 [K,N] -> bf16 [N,K] ---------
__global__ __launch_bounds__(256)
void transpose_conv(const float* __restrict__ src, __nv_bfloat16* __restrict__ dst,
                    int K, int N)
{
    __shared__ float t[32][33];
    int nb = blockIdx.x * 32, kb = blockIdx.y * 32;
    int x = threadIdx.x & 31, y = threadIdx.x >> 5;
    #pragma unroll
    for (int i = 0; i < 32; i += 8) t[y + i][x] = src[(long)(kb + y + i) * N + nb + x];
    __syncthreads();
    #pragma unroll
    for (int i = 0; i < 32; i += 8)
        dst[(long)(nb + y + i) * K + kb + x] = __float2bfloat16(t[x][y + i]);
}

__global__ __launch_bounds__(256)
void scores_init(const float* __restrict__ ba2)
{
    g_scores_t[blockIdx.x * 256 + threadIdx.x] = ba2[0];
}

// ---------------- mma.sync GEMM (HMMA path) -----------------------------------
// CTA tile 128x128, BK=64, 8 warps (2 m x 4 n), warp tile 64x32.
// __launch_bounds__(256,2): cap 128 regs -> 2 CTAs/SM (occ 25%).
// MODE 0: A = emb fp32 (LDG+cvt, 2 batches of 16 regs), B = g_Wt1; GELU -> g_H
// MODE 1: A = g_H bf16 (cp.async), B = g_Wt2; fused tanh-dot -> atomic scores
#define STAGE 32768            // A 128x64 bf16 (16KB) + B 128x64 bf16 (16KB)
#define SMEM_REQ (2 * STAGE + 1024)

template<int KDIM, int MODE>
__global__ __launch_bounds__(256, 2)
void mma_gemm(const float* __restrict__ Af, const float* __restrict__ biasp,
              const float* __restrict__ Wa2p, const float* __restrict__ ba2p)
{
    extern __shared__ unsigned char smem[];
    constexpr int NCH = KDIM / 64;
    const int tid = threadIdx.x, warp = tid >> 5, lane = tid & 31;
    const int wm = warp >> 2, wn = warp & 3;
    const long row0 = (long)blockIdx.y * 128;
    const int col0 = blockIdx.x * 128;

    uint32_t sbb = smem_u32(smem);
    float* bias_s = (float*)(smem + 2 * STAGE);
    float* w2_s = bias_s + 128;
    if (tid < 128) {
        bias_s[tid] = biasp[col0 + tid];
        if (MODE == 1) w2_s[tid] = Wa2p[col0 + tid];
    }

    const __nv_bfloat16* Bt = (MODE == 0) ? g_Wt1 : g_Wt2;

    // MODE 0: A fp32 LDG -> bf16 STS, two batches of 4 float4 (16 live regs)
    auto stageA = [&](int sbuf, int kc) {
        #pragma unroll
        for (int h = 0; h < 2; h++) {
            float4 v[4];
            #pragma unroll
            for (int b = 0; b < 2; b++) {
                int u = tid + 256 * (h * 2 + b), row = u >> 3, cu = u & 7;
                const float4* s = (const float4*)(Af + (row0 + row) * (long)KDIM + kc * 64 + cu * 8);
                v[2 * b] = s[0]; v[2 * b + 1] = s[1];
            }
            #pragma unroll
            for (int b = 0; b < 2; b++) {
                int u = tid + 256 * (h * 2 + b), row = u >> 3, cu = u & 7;
                uint4 p;
                p.x = bf2u(__floats2bfloat162_rn(v[2*b].x,   v[2*b].y));
                p.y = bf2u(__floats2bfloat162_rn(v[2*b].z,   v[2*b].w));
                p.z = bf2u(__floats2bfloat162_rn(v[2*b+1].x, v[2*b+1].y));
                p.w = bf2u(__floats2bfloat162_rn(v[2*b+1].z, v[2*b+1].w));
                *(uint4*)(smem + sbuf * STAGE + SWZ((uint32_t)(row * 128 + cu * 16))) = p;
            }
        }
    };
    auto cpA = [&](int sbuf, int kc) {
        #pragma unroll
        for (int i = 0; i < 4; i++) {
            int u = tid + 256 * i, row = u >> 3, cu = u & 7;
            CP16(sbb + sbuf * STAGE + SWZ((uint32_t)(row * 128 + cu * 16)),
                 (const void*)(g_H + (row0 + row) * (long)KDIM + kc * 64 + cu * 8));
        }
    };
    auto cpB = [&](int sbuf, int kc) {
        #pragma unroll
        for (int i = 0; i < 4; i++) {
            int u = tid + 256 * i, row = u >> 3, cu = u & 7;
            CP16(sbb + sbuf * STAGE + 16384 + SWZ((uint32_t)(row * 128 + cu * 16)),
                 (const void*)(Bt + (col0 + row) * (long)KDIM + kc * 64 + cu * 8));
        }
    };

    float acc[4][4][4];
    #pragma unroll
    for (int mi = 0; mi < 4; mi++)
        #pragma unroll
        for (int ni = 0; ni < 4; ni++)
            #pragma unroll
            for (int q = 0; q < 4; q++) acc[mi][ni][q] = 0.0f;

    // prologue: chunk 0 into buf 0
    cpB(0, 0);
    CP_COMMIT;
    if (MODE == 0) stageA(0, 0); else { cpA(0, 0); CP_COMMIT; }
    CP_WAIT0;
    __syncthreads();

    #pragma unroll 1
    for (int kc = 0; kc < NCH; kc++) {
        const int s = kc & 1;
        if (kc + 1 < NCH) {
            cpB(s ^ 1, kc + 1);
            CP_COMMIT;
            if (MODE == 0) stageA(s ^ 1, kc + 1);   // buffer s^1 free since prev sync
            else { cpA(s ^ 1, kc + 1); CP_COMMIT; }
        }
        uint32_t Ab = sbb + s * STAGE, Bb = Ab + 16384;
        #pragma unroll
        for (int kk = 0; kk < 4; kk++) {
            uint32_t af[4][4], bfr[4][2];
            #pragma unroll
            for (int mi = 0; mi < 4; mi++) {
                int row = wm * 64 + mi * 16 + (lane & 15);
                uint32_t ad = Ab + SWZ((uint32_t)(row * 128 + kk * 32 + ((lane >> 4) << 4)));
                asm volatile("ldmatrix.sync.aligned.m8n8.x4.shared.b16 {%0,%1,%2,%3},[%4];"
                    : "=r"(af[mi][0]), "=r"(af[mi][1]), "=r"(af[mi][2]), "=r"(af[mi][3])
                    : "r"(ad));
            }
            // B: x4 loads two 8-row n-tiles (ni, ni+1) at once
            #pragma unroll
            for (int nj = 0; nj < 2; nj++) {
                int row = wn * 32 + nj * 16 + ((lane >> 4) << 3) + (lane & 7);
                uint32_t bd = Bb + SWZ((uint32_t)(row * 128 + kk * 32 + (((lane >> 3) & 1) << 4)));
                asm volatile("ldmatrix.sync.aligned.m8n8.x4.shared.b16 {%0,%1,%2,%3},[%4];"
                    : "=r"(bfr[2*nj][0]), "=r"(bfr[2*nj][1]),
                      "=r"(bfr[2*nj+1][0]), "=r"(bfr[2*nj+1][1])
                    : "r"(bd));
            }
            #pragma unroll
            for (int mi = 0; mi < 4; mi++)
                #pragma unroll
                for (int ni = 0; ni < 4; ni++)
                    asm volatile("mma.sync.aligned.m16n8k16.row.col.f32.bf16.bf16.f32 "
                        "{%0,%1,%2,%3},{%4,%5,%6,%7},{%8,%9},{%0,%1,%2,%3};"
                        : "+f"(acc[mi][ni][0]), "+f"(acc[mi][ni][1]),
                          "+f"(acc[mi][ni][2]), "+f"(acc[mi][ni][3])
                        : "r"(af[mi][0]), "r"(af[mi][1]), "r"(af[mi][2]), "r"(af[mi][3]),
                          "r"(bfr[ni][0]), "r"(bfr[ni][1]));
        }
        CP_WAIT0;
        __syncthreads();
    }

    // ---- epilogue ----
    if (MODE == 0) {
        #pragma unroll
        for (int mi = 0; mi < 4; mi++) {
            long r0 = row0 + wm * 64 + mi * 16 + (lane >> 2);
            #pragma unroll
            for (int ni = 0; ni < 4; ni++) {
                int col = wn * 32 + ni * 8 + ((lane & 3) << 1);
                float b0 = bias_s[col], b1 = bias_s[col + 1];
                float* c = acc[mi][ni];
                uint32_t p0 = bf2u(__floats2bfloat162_rn(gelu_exact(c[0] + b0), gelu_exact(c[1] + b1)));
                uint32_t p1 = bf2u(__floats2bfloat162_rn(gelu_exact(c[2] + b0), gelu_exact(c[3] + b1)));
                *(uint32_t*)(g_H + r0 * HID + col0 + col) = p0;
                *(uint32_t*)(g_H + (r0 + 8) * HID + col0 + col) = p1;
            }
        }
    } else {
        #pragma unroll
        for (int mi = 0; mi < 4; mi++) {
            float s0 = 0.f, s1 = 0.f;
            #pragma unroll
            for (int ni = 0; ni < 4; ni++) {
                int col = wn * 32 + ni * 8 + ((lane & 3) << 1);
                float b0 = bias_s[col], b1 = bias_s[col + 1];
                float w0 = w2_s[col], w1 = w2_s[col + 1];
                float* c = acc[mi][ni];
                s0 += tanhf(c[0] + b0) * w0 + tanhf(c[1] + b1) * w1;
                s1 += tanhf(c[2] + b0) * w0 + tanhf(c[3] + b1) * w1;
            }
            s0 += __shfl_xor_sync(0xffffffffu, s0, 1);
            s0 += __shfl_xor_sync(0xffffffffu, s0, 2);
            s1 += __shfl_xor_sync(0xffffffffu, s1, 1);
            s1 += __shfl_xor_sync(0xffffffffu, s1, 2);
            if ((lane & 3) == 0) {
                long r0 = row0 + wm * 64 + mi * 16 + (lane >> 2);
                long r1 = r0 + 8;
                atomicAdd(&g_scores_t[(r0 & 15) * MPER + (r0 >> 4)], s0);
                atomicAdd(&g_scores_t[(r1 & 15) * MPER + (r1 >> 4)], s1);
            }
        }
    }
}

// ---------------- per-region softmax stats ------------------------------------
__global__ __launch_bounds__(256)
void region_softmax_stats()
{
    int r = blockIdx.x, tid = threadIdx.x;
    __shared__ float red[256];
    const float* sp = g_scores_t + r * MPER;
    float mx = -1e30f;
    for (int m = tid; m < MPER; m += 256) mx = fmaxf(mx, sp[m]);
    red[tid] = mx; __syncthreads();
    for (int s = 128; s; s >>= 1) { if (tid < s) red[tid] = fmaxf(red[tid], red[tid + s]); __syncthreads(); }
    mx = red[0]; __syncthreads();
    float se = 0.f;
    for (int m = tid; m < MPER; m += 256) se += expf(sp[m] - mx);
    red[tid] = se; __syncthreads();
    for (int s = 128; s; s >>= 1) { if (tid < s) red[tid] += red[tid + s]; __syncthreads(); }
    if (tid == 0) { g_stats[r] = mx; g_stats[16 + r] = red[0]; }
}

// ---------------- weighted pooling -------------------------------------------
__global__ __launch_bounds__(256)
void region_pool()
{
    int r = blockIdx.x, chunk = blockIdx.y, tid = threadIdx.x;
    __shared__ float w[MPER];
    __shared__ float part[256];
    float mx = g_stats[r], inv = 1.0f / g_stats[16 + r];
    const float* sp = g_scores_t + r * MPER;
    for (int m = tid; m < MPER; m += 256) w[m] = expf(sp[m] - mx);
    __syncthreads();
    int h = chunk * 128 + (tid & 127);
    int half = tid >> 7;
    float acc = 0.f;
    for (int m = half; m < MPER; m += 2)
        acc += w[m] * __bfloat162float(g_H[((long)(m * NREG + r)) * HID + h]);
    part[tid] = acc; __syncthreads();
    if (half == 0) g_rf[r * HID + h] = (part[tid] + part[tid + 128]) * inv;
}

// ---------------- tail ---------------------------------------------------------
__global__ __launch_bounds__(512)
void tail_kernel(const float* __restrict__ Ws,  const float* __restrict__ bs,
                 const float* __restrict__ Wsa1,const float* __restrict__ bsa1,
                 const float* __restrict__ Wsa2,const float* __restrict__ bsa2,
                 const float* __restrict__ Wc1, const float* __restrict__ bc1,
                 const float* __restrict__ Wc2, const float* __restrict__ bc2,
                 float* __restrict__ out)
{
    __shared__ float se[NREG * HID];
    __shared__ float sattn[NREG];
    __shared__ float srep[HID];
    __shared__ float c1[HHALF];
    __shared__ float red[64];
    int tid = threadIdx.x;

    {
        int j = tid;
        float acc[NREG];
        #pragma unroll
        for (int r = 0; r < NREG; r++) acc[r] = 0.f;
        for (int k = 0; k < HID; k++) {
            float wv = Ws[k * HID + j];
            #pragma unroll
            for (int r = 0; r < NREG; r++) acc[r] += g_rf[r * HID + k] * wv;
        }
        #pragma unroll
        for (int r = 0; r < NREG; r++)
            se[r * HID + j] = gelu_exact(acc[r] + bs[j]);
    }
    if (tid < NREG) sattn[tid] = 0.f;
    __syncthreads();

    {
        int j = tid & 255;
        int g = tid >> 8;
        for (int r = g * 8; r < g * 8 + 8; r++) {
            float acc = 0.f;
            for (int k = 0; k < HID; k++) acc += se[r * HID + k] * Wsa1[k * HHALF + j];
            float u = tanhf(acc + bsa1[j]);
            atomicAdd(&sattn[r], u * Wsa2[j]);
        }
    }
    __syncthreads();

    if (tid == 0) {
        float mx = -1e30f;
        for (int r = 0; r < NREG; r++) { sattn[r] += bsa2[0]; mx = fmaxf(mx, sattn[r]); }
        float s = 0.f;
        for (int r = 0; r < NREG; r++) { sattn[r] = expf(sattn[r] - mx); s += sattn[r]; }
        for (int r = 0; r < NREG; r++) sattn[r] /= s;
    }
    __syncthreads();

    {
        float acc = 0.f;
        #pragma unroll
        for (int r = 0; r < NREG; r++) acc += sattn[r] * se[r * HID + tid];
        srep[tid] = acc;
    }
    __syncthreads();

    if (tid < HHALF) {
        float acc = 0.f;
        for (int k = 0; k < HID; k++) acc += srep[k] * Wc1[k * HHALF + tid];
        c1[tid] = gelu_exact(acc + bc1[tid]);
    }
    __syncthreads();

    if (tid < 64) {
        int o = tid & 1, p = tid >> 1;
        float acc = 0.f;
        for (int k = p; k < HHALF; k += 32) acc += c1[k] * Wc2[k * 2 + o];
        red[tid] = acc;
    }
    __syncthreads();
    if (tid < 2) {
        float acc = bc2[tid];
        #pragma unroll
        for (int p = 0; p < 32; p++) acc += red[p * 2 + tid];
        out[tid] = acc;
    }
}

// ---------------- launch ------------------------------------------------------
extern "C" void kernel_launch(void* const* d_in, const int* in_sizes, int n_in,
                              void* d_out, int out_size)
{
    const float* emb  = (const float*)d_in[0];
    const float* W1   = (const float*)d_in[1];
    const float* b1   = (const float*)d_in[2];
    const float* Wa1  = (const float*)d_in[3];
    const float* ba1  = (const float*)d_in[4];
    const float* Wa2  = (const float*)d_in[5];
    const float* ba2  = (const float*)d_in[6];
    const float* Ws   = (const float*)d_in[7];
    const float* bs   = (const float*)d_in[8];
    const float* Wsa1 = (const float*)d_in[9];
    const float* bsa1 = (const float*)d_in[10];
    const float* Wsa2 = (const float*)d_in[11];
    const float* bsa2 = (const float*)d_in[12];
    const float* Wc1  = (const float*)d_in[13];
    const float* bc1  = (const float*)d_in[14];
    const float* Wc2  = (const float*)d_in[15];
    const float* bc2  = (const float*)d_in[16];
    float* out = (float*)d_out;

    cudaFuncSetAttribute(mma_gemm<DIM, 0>, cudaFuncAttributeMaxDynamicSharedMemorySize, SMEM_REQ);
    cudaFuncSetAttribute(mma_gemm<HID, 1>, cudaFuncAttributeMaxDynamicSharedMemorySize, SMEM_REQ);

    __nv_bfloat16 *wt1, *wt2;
    cudaGetSymbolAddress((void**)&wt1, g_Wt1);
    cudaGetSymbolAddress((void**)&wt2, g_Wt2);
    transpose_conv<<<dim3(HID / 32, DIM / 32), 256>>>(W1, wt1, DIM, HID);
    transpose_conv<<<dim3(HHALF / 32, HID / 32), 256>>>(Wa1, wt2, HID, HHALF);
    scores_init<<<NTOK / 256, 256>>>(ba2);

    // K1: region encoder (65536x1024 @ 1024x512) + GELU -> g_H
    mma_gemm<DIM, 0><<<dim3(HID / 128, NTOK / 128), 256, SMEM_REQ>>>(emb, b1, nullptr, nullptr);
    // K2: attention hidden (65536x512 @ 512x256) + fused tanh-dot -> scores
    mma_gemm<HID, 1><<<dim3(HHALF / 128, NTOK / 128), 256, SMEM_REQ>>>(nullptr, ba1, Wa2, ba2);

    region_softmax_stats<<<NREG, 256>>>();
    region_pool<<<dim3(NREG, HID / 128), 256>>>();
    tail_kernel<<<1, 512>>>(Ws, bs, Wsa1, bsa1, Wsa2, bsa2, Wc1, bc1, Wc2, bc2, out);
}

// round 13
// speedup vs baseline: 1.7095x; 1.1088x over previous
#include <cuda_runtime.h>
#include <cuda_bf16.h>
#include <cstdint>

// Problem dims
#define NTOK 65536
#define DIM  1024
#define HID  512
#define HHALF 256
#define NREG 16
#define MPER 4096

// ---------------- device scratch ----------------
__device__ __nv_bfloat16 g_H[(long)NTOK * HID];       // region_emb post-GELU (bf16)
__device__ __nv_bfloat16 g_Wt1[HID * DIM];            // W1^T  [512,1024] bf16
__device__ __nv_bfloat16 g_Wt2[HHALF * HID];          // Wa1^T [256,512] bf16
__device__ float g_scores_t[NTOK];                    // region-transposed: [r][m]
__device__ float g_stats[32];                         // [0:16) max, [16:32) sumexp
__device__ float g_rf[NREG * HID];
__device__ float2 g_pp[512 * NREG * 256];             // pooling partials [blk][r][cpair]

__device__ __forceinline__ float gelu_exact(float v) {
    return 0.5f * v * (1.0f + erff(v * 0.7071067811865475f));
}

// ---------------- helpers ----------------
__device__ __forceinline__ uint32_t smem_u32(const void* p) {
    uint32_t a;
    asm("{ .reg .u64 t; cvta.to.shared.u64 t, %1; cvt.u32.u64 %0, t; }" : "=r"(a) : "l"(p));
    return a;
}
__device__ __forceinline__ uint32_t bf2u(__nv_bfloat162 v) { return *reinterpret_cast<uint32_t*>(&v); }

#define SWZ(o) ((o) ^ (((o) >> 3) & 0x70))
#define CP16(d, s) asm volatile("cp.async.cg.shared.global [%0],[%1],16;" :: "r"(d), "l"(s))
#define CP_COMMIT  asm volatile("cp.async.commit_group;" ::: "memory")
#define CP_WAIT0   asm volatile("cp.async.wait_group 0;" ::: "memory")
#define CP_WAIT1   asm volatile("cp.async.wait_group 1;" ::: "memory")

// ---------------- weight transpose+convert: fp32 [K,N] -> bf16 [N,K] ---------
__global__ __launch_bounds__(256)
void transpose_conv(const float* __restrict__ src, __nv_bfloat16* __restrict__ dst,
                    int K, int N)
{
    __shared__ float t[32][33];
    int nb = blockIdx.x * 32, kb = blockIdx.y * 32;
    int x = threadIdx.x & 31, y = threadIdx.x >> 5;
    #pragma unroll
    for (int i = 0; i < 32; i += 8) t[y + i][x] = src[(long)(kb + y + i) * N + nb + x];
    __syncthreads();
    #pragma unroll
    for (int i = 0; i < 32; i += 8)
        dst[(long)(nb + y + i) * K + kb + x] = __float2bfloat16(t[x][y + i]);
}

// ---------------- unified mma.sync GEMM ---------------------------------------
// CTA tile 128x256, 512 threads (16 warps, 4m x 4n), warp tile 32x64, BK=64,
// 3-stage cp.async pipeline.
// MODE 0: A = emb fp32 (in-kernel cvt), B = g_Wt1, GELU -> g_H. grid (2, 512)
// MODE 1: A = g_H bf16 (cp.async), B = g_Wt2, full-N tanh-dot -> direct scores. grid (1, 512)
#define SSTAGE 49152               // A 128x64 bf16 (16KB) + B 256x64 bf16 (32KB)
// bias 1KB + w2 1KB + sp 2KB after the 3 stage buffers
#define SMEM_REQ (3 * SSTAGE + 4096)

template<int KDIM, int MODE>
__global__ __launch_bounds__(512, 1)
void mma_gemm(const float* __restrict__ Af, const float* __restrict__ biasp,
              const float* __restrict__ Wa2p, const float* __restrict__ ba2p)
{
    extern __shared__ unsigned char smem[];
    constexpr int NCH = KDIM / 64;
    const int tid = threadIdx.x, warp = tid >> 5, lane = tid & 31;
    const int wm = warp >> 2, wn = warp & 3;
    const long row0 = (long)blockIdx.y * 128;
    const int col0 = blockIdx.x * 256;

    uint32_t sbb = smem_u32(smem);
    float* bias_s = (float*)(smem + 3 * SSTAGE);      // 256 floats
    float* w2_s = bias_s + 256;                        // 256 floats
    float* sp = w2_s + 256;                            // 512 floats (MODE1 partials)
    if (tid < 256) {
        bias_s[tid] = biasp[col0 + tid];
        if (MODE == 1) w2_s[tid] = Wa2p[tid];
    }

    const __nv_bfloat16* Bt = (MODE == 0) ? g_Wt1 : g_Wt2;

    auto stage = [&](int sbuf, int kc) {
        uint32_t ab = sbb + sbuf * SSTAGE;
        if (MODE == 0) {
            // A fp32 -> bf16: thread handles row tid>>2, 16 cols
            int row = tid >> 2, q = tid & 3;
            const float4* s4 = (const float4*)(Af + (row0 + row) * (long)KDIM + kc * 64 + q * 16);
            float4 v0 = s4[0], v1 = s4[1], v2 = s4[2], v3 = s4[3];
            uint4 p0, p1;
            p0.x = bf2u(__floats2bfloat162_rn(v0.x, v0.y));
            p0.y = bf2u(__floats2bfloat162_rn(v0.z, v0.w));
            p0.z = bf2u(__floats2bfloat162_rn(v1.x, v1.y));
            p0.w = bf2u(__floats2bfloat162_rn(v1.z, v1.w));
            p1.x = bf2u(__floats2bfloat162_rn(v2.x, v2.y));
            p1.y = bf2u(__floats2bfloat162_rn(v2.z, v2.w));
            p1.z = bf2u(__floats2bfloat162_rn(v3.x, v3.y));
            p1.w = bf2u(__floats2bfloat162_rn(v3.z, v3.w));
            uint32_t o = (uint32_t)(row * 128 + q * 32);
            *(uint4*)(smem + sbuf * SSTAGE + SWZ(o)) = p0;
            *(uint4*)(smem + sbuf * SSTAGE + SWZ(o + 16)) = p1;
        } else {
            #pragma unroll
            for (int i = 0; i < 2; i++) {
                int u = tid + 512 * i, row = u >> 3, cu = u & 7;
                CP16(ab + SWZ((uint32_t)(row * 128 + cu * 16)),
                     (const void*)(g_H + (row0 + row) * (long)KDIM + kc * 64 + cu * 8));
            }
        }
        uint32_t bb = ab + 16384;
        #pragma unroll
        for (int i = 0; i < 4; i++) {
            int u = tid + 512 * i, row = u >> 3, cu = u & 7;
            CP16(bb + SWZ((uint32_t)(row * 128 + cu * 16)),
                 (const void*)(Bt + (col0 + row) * (long)KDIM + kc * 64 + cu * 8));
        }
    };

    float acc[2][8][4];
    #pragma unroll
    for (int mi = 0; mi < 2; mi++)
        #pragma unroll
        for (int ni = 0; ni < 8; ni++)
            #pragma unroll
            for (int q = 0; q < 4; q++) acc[mi][ni][q] = 0.0f;

    stage(0, 0); CP_COMMIT;
    stage(1, 1); CP_COMMIT;

    #pragma unroll 1
    for (int kc = 0; kc < NCH; kc++) {
        const int s = kc % 3;
        if (kc + 1 < NCH) { CP_WAIT1; } else { CP_WAIT0; }
        __syncthreads();
        if (kc + 2 < NCH) { stage((kc + 2) % 3, kc + 2); CP_COMMIT; }

        uint32_t Ab = sbb + s * SSTAGE, Bb = Ab + 16384;
        #pragma unroll
        for (int kk = 0; kk < 4; kk++) {
            uint32_t af[2][4], bfr[8][2];
            #pragma unroll
            for (int mi = 0; mi < 2; mi++) {
                int row = wm * 32 + mi * 16 + (lane & 15);
                uint32_t ad = Ab + SWZ((uint32_t)(row * 128 + kk * 32 + ((lane >> 4) << 4)));
                asm volatile("ldmatrix.sync.aligned.m8n8.x4.shared.b16 {%0,%1,%2,%3},[%4];"
                    : "=r"(af[mi][0]), "=r"(af[mi][1]), "=r"(af[mi][2]), "=r"(af[mi][3])
                    : "r"(ad));
            }
            #pragma unroll
            for (int nj = 0; nj < 4; nj++) {
                int row = wn * 64 + nj * 16 + ((lane >> 4) << 3) + (lane & 7);
                uint32_t bd = Bb + SWZ((uint32_t)(row * 128 + kk * 32 + (((lane >> 3) & 1) << 4)));
                asm volatile("ldmatrix.sync.aligned.m8n8.x4.shared.b16 {%0,%1,%2,%3},[%4];"
                    : "=r"(bfr[2*nj][0]), "=r"(bfr[2*nj][1]),
                      "=r"(bfr[2*nj+1][0]), "=r"(bfr[2*nj+1][1])
                    : "r"(bd));
            }
            #pragma unroll
            for (int mi = 0; mi < 2; mi++)
                #pragma unroll
                for (int ni = 0; ni < 8; ni++)
                    asm volatile("mma.sync.aligned.m16n8k16.row.col.f32.bf16.bf16.f32 "
                        "{%0,%1,%2,%3},{%4,%5,%6,%7},{%8,%9},{%0,%1,%2,%3};"
                        : "+f"(acc[mi][ni][0]), "+f"(acc[mi][ni][1]),
                          "+f"(acc[mi][ni][2]), "+f"(acc[mi][ni][3])
                        : "r"(af[mi][0]), "r"(af[mi][1]), "r"(af[mi][2]), "r"(af[mi][3]),
                          "r"(bfr[ni][0]), "r"(bfr[ni][1]));
        }
    }

    // ---- epilogue ----
    if (MODE == 0) {
        #pragma unroll
        for (int mi = 0; mi < 2; mi++) {
            long r0 = row0 + wm * 32 + mi * 16 + (lane >> 2);
            #pragma unroll
            for (int ni = 0; ni < 8; ni++) {
                int cc = wn * 64 + ni * 8 + ((lane & 3) << 1);
                float b0 = bias_s[cc], b1 = bias_s[cc + 1];
                float* c = acc[mi][ni];
                uint32_t p0 = bf2u(__floats2bfloat162_rn(gelu_exact(c[0] + b0), gelu_exact(c[1] + b1)));
                uint32_t p1 = bf2u(__floats2bfloat162_rn(gelu_exact(c[2] + b0), gelu_exact(c[3] + b1)));
                *(uint32_t*)(g_H + r0 * HID + col0 + cc) = p0;
                *(uint32_t*)(g_H + (r0 + 8) * HID + col0 + cc) = p1;
            }
        }
    } else {
        #pragma unroll
        for (int mi = 0; mi < 2; mi++) {
            float s0 = 0.f, s1 = 0.f;
            #pragma unroll
            for (int ni = 0; ni < 8; ni++) {
                int cc = wn * 64 + ni * 8 + ((lane & 3) << 1);
                float b0 = bias_s[cc], b1 = bias_s[cc + 1];
                float w0 = w2_s[cc], w1 = w2_s[cc + 1];
                float* c = acc[mi][ni];
                s0 += tanhf(c[0] + b0) * w0 + tanhf(c[1] + b1) * w1;
                s1 += tanhf(c[2] + b0) * w0 + tanhf(c[3] + b1) * w1;
            }
            s0 += __shfl_xor_sync(0xffffffffu, s0, 1);
            s0 += __shfl_xor_sync(0xffffffffu, s0, 2);
            s1 += __shfl_xor_sync(0xffffffffu, s1, 1);
            s1 += __shfl_xor_sync(0xffffffffu, s1, 2);
            if ((lane & 3) == 0) {
                int lr = wm * 32 + mi * 16 + (lane >> 2);
                sp[lr * 4 + wn] = s0;
                sp[(lr + 8) * 4 + wn] = s1;
            }
        }
        __syncthreads();
        if (tid < 128) {
            float sc = sp[tid * 4] + sp[tid * 4 + 1] + sp[tid * 4 + 2] + sp[tid * 4 + 3] + ba2p[0];
            long t = row0 + tid;
            g_scores_t[(t & 15) * MPER + (t >> 4)] = sc;
        }
    }
}

// ---------------- per-region softmax stats ------------------------------------
__global__ __launch_bounds__(256)
void region_softmax_stats()
{
    int r = blockIdx.x, tid = threadIdx.x;
    __shared__ float red[256];
    const float* spt = g_scores_t + r * MPER;
    float mx = -1e30f;
    for (int m = tid; m < MPER; m += 256) mx = fmaxf(mx, spt[m]);
    red[tid] = mx; __syncthreads();
    for (int s = 128; s; s >>= 1) { if (tid < s) red[tid] = fmaxf(red[tid], red[tid + s]); __syncthreads(); }
    mx = red[0]; __syncthreads();
    float se = 0.f;
    for (int m = tid; m < MPER; m += 256) se += expf(spt[m] - mx);
    red[tid] = se; __syncthreads();
    for (int s = 128; s; s >>= 1) { if (tid < s) red[tid] += red[tid + s]; __syncthreads(); }
    if (tid == 0) { g_stats[r] = mx; g_stats[16 + r] = red[0]; }
}

// ---------------- pooling: coalesced partials over token blocks ---------------
// grid 512, block 256: CTA handles 128 consecutive tokens x all 512 cols.
__global__ __launch_bounds__(256)
void pool_partial()
{
    __shared__ float wts[128];
    int blk = blockIdx.x, tid = threadIdx.x;
    long base = (long)blk * 128;
    if (tid < 128) {
        long t = base + tid;
        int r = (int)(t & 15);
        wts[tid] = expf(g_scores_t[r * MPER + (t >> 4)] - g_stats[r]);
    }
    __syncthreads();
    int c = tid;  // col-pair 0..255 -> cols 2c, 2c+1
    #pragma unroll 1
    for (int r = 0; r < NREG; r++) {
        float a0 = 0.f, a1 = 0.f;
        #pragma unroll
        for (int i = 0; i < 8; i++) {
            int lr = r + i * 16;
            uint32_t u = *(const uint32_t*)(g_H + (base + lr) * HID + 2 * c);
            __nv_bfloat162 h2 = *reinterpret_cast<__nv_bfloat162*>(&u);
            float w = wts[lr];
            a0 += w * __bfloat162float(h2.x);
            a1 += w * __bfloat162float(h2.y);
        }
        g_pp[(blk * NREG + r) * 256 + c] = make_float2(a0, a1);
    }
}

// grid 16, block 256: reduce over 512 blocks, normalize, write g_rf
__global__ __launch_bounds__(256)
void pool_reduce()
{
    int r = blockIdx.x, c = threadIdx.x;
    float inv = 1.0f / g_stats[16 + r];
    float a0 = 0.f, a1 = 0.f;
    #pragma unroll 4
    for (int blk = 0; blk < 512; blk++) {
        float2 v = g_pp[(blk * NREG + r) * 256 + c];
        a0 += v.x; a1 += v.y;
    }
    g_rf[r * HID + 2 * c]     = a0 * inv;
    g_rf[r * HID + 2 * c + 1] = a1 * inv;
}

// ---------------- tail ---------------------------------------------------------
__global__ __launch_bounds__(512)
void tail_kernel(const float* __restrict__ Ws,  const float* __restrict__ bs,
                 const float* __restrict__ Wsa1,const float* __restrict__ bsa1,
                 const float* __restrict__ Wsa2,const float* __restrict__ bsa2,
                 const float* __restrict__ Wc1, const float* __restrict__ bc1,
                 const float* __restrict__ Wc2, const float* __restrict__ bc2,
                 float* __restrict__ out)
{
    __shared__ float se[NREG * HID];
    __shared__ float sattn[NREG];
    __shared__ float srep[HID];
    __shared__ float c1[HHALF];
    __shared__ float red[64];
    int tid = threadIdx.x;

    {
        int j = tid;
        float acc[NREG];
        #pragma unroll
        for (int r = 0; r < NREG; r++) acc[r] = 0.f;
        for (int k = 0; k < HID; k++) {
            float wv = Ws[k * HID + j];
            #pragma unroll
            for (int r = 0; r < NREG; r++) acc[r] += g_rf[r * HID + k] * wv;
        }
        #pragma unroll
        for (int r = 0; r < NREG; r++)
            se[r * HID + j] = gelu_exact(acc[r] + bs[j]);
    }
    if (tid < NREG) sattn[tid] = 0.f;
    __syncthreads();

    {
        int j = tid & 255;
        int g = tid >> 8;
        for (int r = g * 8; r < g * 8 + 8; r++) {
            float acc = 0.f;
            for (int k = 0; k < HID; k++) acc += se[r * HID + k] * Wsa1[k * HHALF + j];
            float u = tanhf(acc + bsa1[j]);
            atomicAdd(&sattn[r], u * Wsa2[j]);
        }
    }
    __syncthreads();

    if (tid == 0) {
        float mx = -1e30f;
        for (int r = 0; r < NREG; r++) { sattn[r] += bsa2[0]; mx = fmaxf(mx, sattn[r]); }
        float s = 0.f;
        for (int r = 0; r < NREG; r++) { sattn[r] = expf(sattn[r] - mx); s += sattn[r]; }
        for (int r = 0; r < NREG; r++) sattn[r] /= s;
    }
    __syncthreads();

    {
        float acc = 0.f;
        #pragma unroll
        for (int r = 0; r < NREG; r++) acc += sattn[r] * se[r * HID + tid];
        srep[tid] = acc;
    }
    __syncthreads();

    if (tid < HHALF) {
        float acc = 0.f;
        for (int k = 0; k < HID; k++) acc += srep[k] * Wc1[k * HHALF + tid];
        c1[tid] = gelu_exact(acc + bc1[tid]);
    }
    __syncthreads();

    if (tid < 64) {
        int o = tid & 1, p = tid >> 1;
        float acc = 0.f;
        for (int k = p; k < HHALF; k += 32) acc += c1[k] * Wc2[k * 2 + o];
        red[tid] = acc;
    }
    __syncthreads();
    if (tid < 2) {
        float acc = bc2[tid];
        #pragma unroll
        for (int p = 0; p < 32; p++) acc += red[p * 2 + tid];
        out[tid] = acc;
    }
}

// ---------------- launch ------------------------------------------------------
extern "C" void kernel_launch(void* const* d_in, const int* in_sizes, int n_in,
                              void* d_out, int out_size)
{
    const float* emb  = (const float*)d_in[0];
    const float* W1   = (const float*)d_in[1];
    const float* b1   = (const float*)d_in[2];
    const float* Wa1  = (const float*)d_in[3];
    const float* ba1  = (const float*)d_in[4];
    const float* Wa2  = (const float*)d_in[5];
    const float* ba2  = (const float*)d_in[6];
    const float* Ws   = (const float*)d_in[7];
    const float* bs   = (const float*)d_in[8];
    const float* Wsa1 = (const float*)d_in[9];
    const float* bsa1 = (const float*)d_in[10];
    const float* Wsa2 = (const float*)d_in[11];
    const float* bsa2 = (const float*)d_in[12];
    const float* Wc1  = (const float*)d_in[13];
    const float* bc1  = (const float*)d_in[14];
    const float* Wc2  = (const float*)d_in[15];
    const float* bc2  = (const float*)d_in[16];
    float* out = (float*)d_out;

    cudaFuncSetAttribute(mma_gemm<DIM, 0>, cudaFuncAttributeMaxDynamicSharedMemorySize, SMEM_REQ);
    cudaFuncSetAttribute(mma_gemm<HID, 1>, cudaFuncAttributeMaxDynamicSharedMemorySize, SMEM_REQ);

    __nv_bfloat16 *wt1, *wt2;
    cudaGetSymbolAddress((void**)&wt1, g_Wt1);
    cudaGetSymbolAddress((void**)&wt2, g_Wt2);
    transpose_conv<<<dim3(HID / 32, DIM / 32), 256>>>(W1, wt1, DIM, HID);
    transpose_conv<<<dim3(HHALF / 32, HID / 32), 256>>>(Wa1, wt2, HID, HHALF);

    // K1: region encoder (65536x1024 @ 1024x512) + GELU -> g_H
    mma_gemm<DIM, 0><<<dim3(2, NTOK / 128), 512, SMEM_REQ>>>(emb, b1, nullptr, nullptr);
    // K2: attention hidden (65536x512 @ 512x256) + fused tanh-dot -> direct scores
    mma_gemm<HID, 1><<<dim3(1, NTOK / 128), 512, SMEM_REQ>>>(nullptr, ba1, Wa2, ba2);

    region_softmax_stats<<<NREG, 256>>>();
    pool_partial<<<512, 256>>>();
    pool_reduce<<<NREG, 256>>>();
    tail_kernel<<<1, 512>>>(Ws, bs, Wsa1, bsa1, Wsa2, bsa2, Wc1, bc1, Wc2, bc2, out);
}

// round 14
// speedup vs baseline: 3.1250x; 1.8281x over previous
#include <cuda_runtime.h>
#include <cuda_bf16.h>
#include <cstdint>

// Problem dims
#define NTOK 65536
#define DIM  1024
#define HID  512
#define HHALF 256
#define NREG 16
#define MPER 4096

// ---------------- device scratch ----------------
__device__ __nv_bfloat16 g_H[(long)NTOK * HID];       // region_emb post-GELU (bf16)
__device__ __nv_bfloat16 g_Wt1[HID * DIM];            // W1^T  [512,1024] bf16
__device__ __nv_bfloat16 g_Wt2[HHALF * HID];          // Wa1^T [256,512] bf16
__device__ float g_scores_t[NTOK];                    // region-transposed: [r][m]
__device__ float g_stats[32];                         // [0:16) max, [16:32) sumexp
__device__ float g_rf[NREG * HID];
__device__ float g_se[NREG * HID];                    // slide_emb
__device__ float g_sattn[NREG];                       // slide attention raw scores
__device__ float2 g_pp[512 * NREG * 256];             // pooling partials [blk][r][cpair]

__device__ __forceinline__ float gelu_exact(float v) {
    return 0.5f * v * (1.0f + erff(v * 0.7071067811865475f));
}

// ---------------- helpers ----------------
__device__ __forceinline__ uint32_t smem_u32(const void* p) {
    uint32_t a;
    asm("{ .reg .u64 t; cvta.to.shared.u64 t, %1; cvt.u32.u64 %0, t; }" : "=r"(a) : "l"(p));
    return a;
}
__device__ __forceinline__ uint32_t bf2u(__nv_bfloat162 v) { return *reinterpret_cast<uint32_t*>(&v); }

#define SWZ(o) ((o) ^ (((o) >> 3) & 0x70))
#define CP16(d, s) asm volatile("cp.async.cg.shared.global [%0],[%1],16;" :: "r"(d), "l"(s))
#define CP_COMMIT  asm volatile("cp.async.commit_group;" ::: "memory")
#define CP_WAIT0   asm volatile("cp.async.wait_group 0;" ::: "memory")
#define CP_WAIT1   asm volatile("cp.async.wait_group 1;" ::: "memory")

// ---------------- weight transpose+convert: fp32 [K,N] -> bf16 [N,K] ---------
__global__ __launch_bounds__(256)
void transpose_conv(const float* __restrict__ src, __nv_bfloat16* __restrict__ dst,
                    int K, int N)
{
    __shared__ float t[32][33];
    int nb = blockIdx.x * 32, kb = blockIdx.y * 32;
    int x = threadIdx.x & 31, y = threadIdx.x >> 5;
    #pragma unroll
    for (int i = 0; i < 32; i += 8) t[y + i][x] = src[(long)(kb + y + i) * N + nb + x];
    __syncthreads();
    #pragma unroll
    for (int i = 0; i < 32; i += 8)
        dst[(long)(nb + y + i) * K + kb + x] = __float2bfloat16(t[x][y + i]);
}

// ---------------- unified mma.sync GEMM ---------------------------------------
// CTA tile 128x256, 512 threads (16 warps, 4m x 4n), warp tile 32x64, BK=64,
// 3-stage pipeline. MODE 0: A-LDG prefetched into regs one iteration early.
#define SSTAGE 49152               // A 128x64 bf16 (16KB) + B 256x64 bf16 (32KB)
#define SMEM_REQ (3 * SSTAGE + 4096)

template<int KDIM, int MODE>
__global__ __launch_bounds__(512, 1)
void mma_gemm(const float* __restrict__ Af, const float* __restrict__ biasp,
              const float* __restrict__ Wa2p, const float* __restrict__ ba2p)
{
    extern __shared__ unsigned char smem[];
    constexpr int NCH = KDIM / 64;
    const int tid = threadIdx.x, warp = tid >> 5, lane = tid & 31;
    const int wm = warp >> 2, wn = warp & 3;
    const long row0 = (long)blockIdx.y * 128;
    const int col0 = blockIdx.x * 256;

    uint32_t sbb = smem_u32(smem);
    float* bias_s = (float*)(smem + 3 * SSTAGE);      // 256 floats
    float* w2_s = bias_s + 256;                        // 256 floats
    float* sp = w2_s + 256;                            // 512 floats (MODE1 partials)
    if (tid < 256) {
        bias_s[tid] = biasp[col0 + tid];
        if (MODE == 1) w2_s[tid] = Wa2p[tid];
    }

    const __nv_bfloat16* Bt = (MODE == 0) ? g_Wt1 : g_Wt2;

    float4 areg[4];                 // MODE 0: prefetched A (row tid>>2, 16 cols)
    const int arow = tid >> 2, aq = tid & 3;

    auto ldgA = [&](int kc) {       // MODE 0 only: global fp32 -> regs
        const float4* s4 = (const float4*)(Af + (row0 + arow) * (long)KDIM + kc * 64 + aq * 16);
        areg[0] = s4[0]; areg[1] = s4[1]; areg[2] = s4[2]; areg[3] = s4[3];
    };
    auto stsA = [&](int sbuf) {     // MODE 0 only: regs -> bf16 smem
        uint4 p0, p1;
        p0.x = bf2u(__floats2bfloat162_rn(areg[0].x, areg[0].y));
        p0.y = bf2u(__floats2bfloat162_rn(areg[0].z, areg[0].w));
        p0.z = bf2u(__floats2bfloat162_rn(areg[1].x, areg[1].y));
        p0.w = bf2u(__floats2bfloat162_rn(areg[1].z, areg[1].w));
        p1.x = bf2u(__floats2bfloat162_rn(areg[2].x, areg[2].y));
        p1.y = bf2u(__floats2bfloat162_rn(areg[2].z, areg[2].w));
        p1.z = bf2u(__floats2bfloat162_rn(areg[3].x, areg[3].y));
        p1.w = bf2u(__floats2bfloat162_rn(areg[3].z, areg[3].w));
        uint32_t o = (uint32_t)(arow * 128 + aq * 32);
        *(uint4*)(smem + sbuf * SSTAGE + SWZ(o)) = p0;
        *(uint4*)(smem + sbuf * SSTAGE + SWZ(o + 16)) = p1;
    };
    auto cpA = [&](int sbuf, int kc) {  // MODE 1 only
        uint32_t ab = sbb + sbuf * SSTAGE;
        #pragma unroll
        for (int i = 0; i < 2; i++) {
            int u = tid + 512 * i, row = u >> 3, cu = u & 7;
            CP16(ab + SWZ((uint32_t)(row * 128 + cu * 16)),
                 (const void*)(g_H + (row0 + row) * (long)KDIM + kc * 64 + cu * 8));
        }
    };
    auto cpB = [&](int sbuf, int kc) {
        uint32_t bb = sbb + sbuf * SSTAGE + 16384;
        #pragma unroll
        for (int i = 0; i < 4; i++) {
            int u = tid + 512 * i, row = u >> 3, cu = u & 7;
            CP16(bb + SWZ((uint32_t)(row * 128 + cu * 16)),
                 (const void*)(Bt + (col0 + row) * (long)KDIM + kc * 64 + cu * 8));
        }
    };

    float acc[2][8][4];
    #pragma unroll
    for (int mi = 0; mi < 2; mi++)
        #pragma unroll
        for (int ni = 0; ni < 8; ni++)
            #pragma unroll
            for (int q = 0; q < 4; q++) acc[mi][ni][q] = 0.0f;

    // prologue
    if (MODE == 0) {
        ldgA(0); cpB(0, 0); CP_COMMIT; stsA(0);
        ldgA(1); cpB(1, 1); CP_COMMIT; stsA(1);
        ldgA(2);                       // NCH >= 8 always
    } else {
        cpA(0, 0); cpB(0, 0); CP_COMMIT;
        cpA(1, 1); cpB(1, 1); CP_COMMIT;
    }

    #pragma unroll 1
    for (int kc = 0; kc < NCH; kc++) {
        const int s = kc % 3;
        if (kc + 1 < NCH) { CP_WAIT1; } else { CP_WAIT0; }
        __syncthreads();
        if (kc + 2 < NCH) {
            if (MODE == 0) {
                stsA((kc + 2) % 3);            // buffer freed by the sync above
                if (kc + 3 < NCH) ldgA(kc + 3); // prefetch next (hidden under MMA)
            } else {
                cpA((kc + 2) % 3, kc + 2);
            }
            cpB((kc + 2) % 3, kc + 2);
            CP_COMMIT;
        }

        uint32_t Ab = sbb + s * SSTAGE, Bb = Ab + 16384;
        #pragma unroll
        for (int kk = 0; kk < 4; kk++) {
            uint32_t af[2][4], bfr[8][2];
            #pragma unroll
            for (int mi = 0; mi < 2; mi++) {
                int row = wm * 32 + mi * 16 + (lane & 15);
                uint32_t ad = Ab + SWZ((uint32_t)(row * 128 + kk * 32 + ((lane >> 4) << 4)));
                asm volatile("ldmatrix.sync.aligned.m8n8.x4.shared.b16 {%0,%1,%2,%3},[%4];"
                    : "=r"(af[mi][0]), "=r"(af[mi][1]), "=r"(af[mi][2]), "=r"(af[mi][3])
                    : "r"(ad));
            }
            #pragma unroll
            for (int nj = 0; nj < 4; nj++) {
                int row = wn * 64 + nj * 16 + ((lane >> 4) << 3) + (lane & 7);
                uint32_t bd = Bb + SWZ((uint32_t)(row * 128 + kk * 32 + (((lane >> 3) & 1) << 4)));
                asm volatile("ldmatrix.sync.aligned.m8n8.x4.shared.b16 {%0,%1,%2,%3},[%4];"
                    : "=r"(bfr[2*nj][0]), "=r"(bfr[2*nj][1]),
                      "=r"(bfr[2*nj+1][0]), "=r"(bfr[2*nj+1][1])
                    : "r"(bd));
            }
            #pragma unroll
            for (int mi = 0; mi < 2; mi++)
                #pragma unroll
                for (int ni = 0; ni < 8; ni++)
                    asm volatile("mma.sync.aligned.m16n8k16.row.col.f32.bf16.bf16.f32 "
                        "{%0,%1,%2,%3},{%4,%5,%6,%7},{%8,%9},{%0,%1,%2,%3};"
                        : "+f"(acc[mi][ni][0]), "+f"(acc[mi][ni][1]),
                          "+f"(acc[mi][ni][2]), "+f"(acc[mi][ni][3])
                        : "r"(af[mi][0]), "r"(af[mi][1]), "r"(af[mi][2]), "r"(af[mi][3]),
                          "r"(bfr[ni][0]), "r"(bfr[ni][1]));
        }
    }

    // ---- epilogue ----
    if (MODE == 0) {
        #pragma unroll
        for (int mi = 0; mi < 2; mi++) {
            long r0 = row0 + wm * 32 + mi * 16 + (lane >> 2);
            #pragma unroll
            for (int ni = 0; ni < 8; ni++) {
                int cc = wn * 64 + ni * 8 + ((lane & 3) << 1);
                float b0 = bias_s[cc], b1 = bias_s[cc + 1];
                float* c = acc[mi][ni];
                uint32_t p0 = bf2u(__floats2bfloat162_rn(gelu_exact(c[0] + b0), gelu_exact(c[1] + b1)));
                uint32_t p1 = bf2u(__floats2bfloat162_rn(gelu_exact(c[2] + b0), gelu_exact(c[3] + b1)));
                *(uint32_t*)(g_H + r0 * HID + col0 + cc) = p0;
                *(uint32_t*)(g_H + (r0 + 8) * HID + col0 + cc) = p1;
            }
        }
    } else {
        #pragma unroll
        for (int mi = 0; mi < 2; mi++) {
            float s0 = 0.f, s1 = 0.f;
            #pragma unroll
            for (int ni = 0; ni < 8; ni++) {
                int cc = wn * 64 + ni * 8 + ((lane & 3) << 1);
                float b0 = bias_s[cc], b1 = bias_s[cc + 1];
                float w0 = w2_s[cc], w1 = w2_s[cc + 1];
                float* c = acc[mi][ni];
                s0 += tanhf(c[0] + b0) * w0 + tanhf(c[1] + b1) * w1;
                s1 += tanhf(c[2] + b0) * w0 + tanhf(c[3] + b1) * w1;
            }
            s0 += __shfl_xor_sync(0xffffffffu, s0, 1);
            s0 += __shfl_xor_sync(0xffffffffu, s0, 2);
            s1 += __shfl_xor_sync(0xffffffffu, s1, 1);
            s1 += __shfl_xor_sync(0xffffffffu, s1, 2);
            if ((lane & 3) == 0) {
                int lr = wm * 32 + mi * 16 + (lane >> 2);
                sp[lr * 4 + wn] = s0;
                sp[(lr + 8) * 4 + wn] = s1;
            }
        }
        __syncthreads();
        if (tid < 128) {
            float sc = sp[tid * 4] + sp[tid * 4 + 1] + sp[tid * 4 + 2] + sp[tid * 4 + 3] + ba2p[0];
            long t = row0 + tid;
            g_scores_t[(t & 15) * MPER + (t >> 4)] = sc;
        }
    }
}

// ---------------- per-region softmax stats ------------------------------------
__global__ __launch_bounds__(256)
void region_softmax_stats()
{
    int r = blockIdx.x, tid = threadIdx.x;
    __shared__ float red[256];
    const float* spt = g_scores_t + r * MPER;
    float mx = -1e30f;
    for (int m = tid; m < MPER; m += 256) mx = fmaxf(mx, spt[m]);
    red[tid] = mx; __syncthreads();
    for (int s = 128; s; s >>= 1) { if (tid < s) red[tid] = fmaxf(red[tid], red[tid + s]); __syncthreads(); }
    mx = red[0]; __syncthreads();
    float se = 0.f;
    for (int m = tid; m < MPER; m += 256) se += expf(spt[m] - mx);
    red[tid] = se; __syncthreads();
    for (int s = 128; s; s >>= 1) { if (tid < s) red[tid] += red[tid + s]; __syncthreads(); }
    if (tid == 0) { g_stats[r] = mx; g_stats[16 + r] = red[0]; }
}

// ---------------- pooling: coalesced partials over token blocks ---------------
__global__ __launch_bounds__(256)
void pool_partial()
{
    __shared__ float wts[128];
    int blk = blockIdx.x, tid = threadIdx.x;
    long base = (long)blk * 128;
    if (tid < 128) {
        long t = base + tid;
        int r = (int)(t & 15);
        wts[tid] = expf(g_scores_t[r * MPER + (t >> 4)] - g_stats[r]);
    }
    __syncthreads();
    int c = tid;
    #pragma unroll 1
    for (int r = 0; r < NREG; r++) {
        float a0 = 0.f, a1 = 0.f;
        #pragma unroll
        for (int i = 0; i < 8; i++) {
            int lr = r + i * 16;
            uint32_t u = *(const uint32_t*)(g_H + (base + lr) * HID + 2 * c);
            __nv_bfloat162 h2 = *reinterpret_cast<__nv_bfloat162*>(&u);
            float w = wts[lr];
            a0 += w * __bfloat162float(h2.x);
            a1 += w * __bfloat162float(h2.y);
        }
        g_pp[(blk * NREG + r) * 256 + c] = make_float2(a0, a1);
    }
}

// grid 16, block 512: reduce over 512 blocks (split halves), normalize
__global__ __launch_bounds__(512)
void pool_reduce()
{
    __shared__ float2 pr[512];
    int r = blockIdx.x, tid = threadIdx.x;
    int c = tid & 255, h = tid >> 8;
    float a0 = 0.f, a1 = 0.f;
    #pragma unroll 4
    for (int blk = h * 256; blk < h * 256 + 256; blk++) {
        float2 v = g_pp[(blk * NREG + r) * 256 + c];
        a0 += v.x; a1 += v.y;
    }
    pr[tid] = make_float2(a0, a1);
    __syncthreads();
    if (h == 0) {
        float inv = 1.0f / g_stats[16 + r];
        float2 o = pr[tid], o2 = pr[tid + 256];
        g_rf[r * HID + 2 * c]     = (o.x + o2.x) * inv;
        g_rf[r * HID + 2 * c + 1] = (o.y + o2.y) * inv;
    }
}

// ---------------- slide encoder + attention score, one CTA per region ---------
__global__ __launch_bounds__(512)
void slide_enc(const float* __restrict__ Ws,  const float* __restrict__ bs,
               const float* __restrict__ Wsa1,const float* __restrict__ bsa1,
               const float* __restrict__ Wsa2,const float* __restrict__ bsa2)
{
    __shared__ float rf[HID];
    __shared__ float se[HID];
    __shared__ float part[512];
    int r = blockIdx.x, tid = threadIdx.x;
    rf[tid] = g_rf[r * HID + tid];
    __syncthreads();

    // se[j] = gelu(sum_k rf[k] * Ws[k*512 + j] + bs[j])
    float acc = 0.f;
    #pragma unroll 8
    for (int k = 0; k < HID; k++) acc += rf[k] * Ws[k * HID + tid];
    float sev = gelu_exact(acc + bs[tid]);
    se[tid] = sev;
    g_se[r * HID + tid] = sev;
    __syncthreads();

    // u_j = sum_k se[k] * Wsa1[k*256 + j], k split in 2 halves
    int j = tid & 255, h = tid >> 8;
    float p = 0.f;
    #pragma unroll 8
    for (int k = h * 256; k < h * 256 + 256; k++) p += se[k] * Wsa1[k * HHALF + j];
    part[tid] = p;
    __syncthreads();
    if (tid < 256)
        part[tid] = tanhf(part[tid] + part[tid + 256] + bsa1[tid]) * Wsa2[tid];
    __syncthreads();
    for (int s = 128; s; s >>= 1) { if (tid < s) part[tid] += part[tid + s]; __syncthreads(); }
    if (tid == 0) g_sattn[r] = part[0] + bsa2[0];
}

// ---------------- final: softmax-16 + slide_rep + classifier ------------------
__global__ __launch_bounds__(512)
void tail_final(const float* __restrict__ Wc1, const float* __restrict__ bc1,
                const float* __restrict__ Wc2, const float* __restrict__ bc2,
                float* __restrict__ out)
{
    __shared__ float w[NREG];
    __shared__ float srep[HID];
    __shared__ float c1[HHALF];
    __shared__ float red[64];
    int tid = threadIdx.x;

    if (tid == 0) {
        float mx = -1e30f;
        for (int r = 0; r < NREG; r++) mx = fmaxf(mx, g_sattn[r]);
        float s = 0.f;
        for (int r = 0; r < NREG; r++) { w[r] = expf(g_sattn[r] - mx); s += w[r]; }
        for (int r = 0; r < NREG; r++) w[r] /= s;
    }
    __syncthreads();

    float a = 0.f;
    #pragma unroll
    for (int r = 0; r < NREG; r++) a += w[r] * g_se[r * HID + tid];
    srep[tid] = a;
    __syncthreads();

    if (tid < HHALF) {
        float acc = 0.f;
        #pragma unroll 8
        for (int k = 0; k < HID; k++) acc += srep[k] * Wc1[k * HHALF + tid];
        c1[tid] = gelu_exact(acc + bc1[tid]);
    }
    __syncthreads();

    if (tid < 64) {
        int o = tid & 1, p = tid >> 1;
        float acc = 0.f;
        for (int k = p; k < HHALF; k += 32) acc += c1[k] * Wc2[k * 2 + o];
        red[tid] = acc;
    }
    __syncthreads();
    if (tid < 2) {
        float acc = bc2[tid];
        #pragma unroll
        for (int p = 0; p < 32; p++) acc += red[p * 2 + tid];
        out[tid] = acc;
    }
}

// ---------------- launch ------------------------------------------------------
extern "C" void kernel_launch(void* const* d_in, const int* in_sizes, int n_in,
                              void* d_out, int out_size)
{
    const float* emb  = (const float*)d_in[0];
    const float* W1   = (const float*)d_in[1];
    const float* b1   = (const float*)d_in[2];
    const float* Wa1  = (const float*)d_in[3];
    const float* ba1  = (const float*)d_in[4];
    const float* Wa2  = (const float*)d_in[5];
    const float* ba2  = (const float*)d_in[6];
    const float* Ws   = (const float*)d_in[7];
    const float* bs   = (const float*)d_in[8];
    const float* Wsa1 = (const float*)d_in[9];
    const float* bsa1 = (const float*)d_in[10];
    const float* Wsa2 = (const float*)d_in[11];
    const float* bsa2 = (const float*)d_in[12];
    const float* Wc1  = (const float*)d_in[13];
    const float* bc1  = (const float*)d_in[14];
    const float* Wc2  = (const float*)d_in[15];
    const float* bc2  = (const float*)d_in[16];
    float* out = (float*)d_out;

    cudaFuncSetAttribute(mma_gemm<DIM, 0>, cudaFuncAttributeMaxDynamicSharedMemorySize, SMEM_REQ);
    cudaFuncSetAttribute(mma_gemm<HID, 1>, cudaFuncAttributeMaxDynamicSharedMemorySize, SMEM_REQ);

    __nv_bfloat16 *wt1, *wt2;
    cudaGetSymbolAddress((void**)&wt1, g_Wt1);
    cudaGetSymbolAddress((void**)&wt2, g_Wt2);
    transpose_conv<<<dim3(HID / 32, DIM / 32), 256>>>(W1, wt1, DIM, HID);
    transpose_conv<<<dim3(HHALF / 32, HID / 32), 256>>>(Wa1, wt2, HID, HHALF);

    // K1: region encoder (65536x1024 @ 1024x512) + GELU -> g_H
    mma_gemm<DIM, 0><<<dim3(2, NTOK / 128), 512, SMEM_REQ>>>(emb, b1, nullptr, nullptr);
    // K2: attention hidden (65536x512 @ 512x256) + fused tanh-dot -> direct scores
    mma_gemm<HID, 1><<<dim3(1, NTOK / 128), 512, SMEM_REQ>>>(nullptr, ba1, Wa2, ba2);

    region_softmax_stats<<<NREG, 256>>>();
    pool_partial<<<512, 256>>>();
    pool_reduce<<<NREG, 512>>>();
    slide_enc<<<NREG, 512>>>(Ws, bs, Wsa1, bsa1, Wsa2, bsa2);
    tail_final<<<1, 512>>>(Wc1, bc1, Wc2, bc2, out);
}